// round 6
// baseline (speedup 1.0000x reference)
#include <cuda_runtime.h>
#include <cuda_bf16.h>
#include <cstdint>

// Blur_82471962018173: depthwise separable 4x4 FIR ([1,3,3,1]/4 per axis),
// input (4,128,513,513) f32, pad=1 both sides, output (4,128,512,512) f32.
//
// R6: persistent cp.async ring pipeline. 1776 blocks (148 SM x 12) each
// static-stride over 4096 strips (64 rows x 512 cols). No wave-quantization
// tail; adjacent y-strips on adjacent bids share halo rows in L2.

#define W_IN   513
#define W_OUT  512
#define ROWS   64
#define YSTRIPS (W_OUT / ROWS)        // 8
#define NSTRIP  (512 * YSTRIPS)       // 4096
#define NT     128
#define DEPTH  6
#define SLOTS  8
#define SSTR   520   // floats per ring slot (515 used)
#define GRID   (148 * 12)

__device__ __forceinline__ void cp4(uint32_t dst, const float* src, int sz) {
    asm volatile("cp.async.ca.shared.global [%0], [%1], 4, %2;"
                 :: "r"(dst), "l"(src), "r"(sz));
}

__global__ __launch_bounds__(NT, 12)
void blur_kernel(const float* __restrict__ in, float* __restrict__ out) {
    __shared__ float ring[SLOTS][SSTR];   // ring[s][i] holds input x = i-1

    const int t  = threadIdx.x;
    const int x0 = t << 2;                // output cols x0..x0+3

    // thread-invariant column validity / offsets
    const int  c0   = t - 1;              // main cols: c0 + j*NT, j=0..3
    const int  sz0  = (t == 0) ? 0 : 4;   // only i==0 (x=-1) invalid
    const bool edge = (t < 3);            // i = 512+t -> x = 511..513
    const int  sz_e = (t < 2) ? 4 : 0;    // x=513 invalid
    const int  ce   = 511 + t;

    const uint32_t sring = (uint32_t)__cvta_generic_to_shared(&ring[0][0]);

    for (int s = blockIdx.x; s < NSTRIP; s += GRID) {
        const int plane = s >> 3;              // 0..511
        const int y0    = (s & 7) * ROWS;

        const float* __restrict__ inp  = in  + (size_t)plane * (W_IN  * W_IN);
        float*       __restrict__ outp = out + (size_t)plane * (W_OUT * W_OUT);
        const float* rp = inp + (size_t)(y0 - 1) * W_IN;

        // protect ring slots from previous strip's readers
        asm volatile("cp.async.wait_group 0;");
        __syncthreads();

        auto issue_row = [&](int r) {
            const int yy = y0 - 1 + r;
            const bool rowok = ((unsigned)yy < (unsigned)W_IN); // warp-uniform
            const uint32_t sb = sring + (uint32_t)(r & (SLOTS - 1)) * (SSTR * 4);
            const float* rr = rowok ? (rp + (size_t)r * W_IN) : inp;
            cp4(sb + (t + 0 * NT) * 4, rr + c0 + 0 * NT, rowok ? sz0 : 0);
            cp4(sb + (t + 1 * NT) * 4, rr + c0 + 1 * NT, rowok ? 4 : 0);
            cp4(sb + (t + 2 * NT) * 4, rr + c0 + 2 * NT, rowok ? 4 : 0);
            cp4(sb + (t + 3 * NT) * 4, rr + c0 + 3 * NT, rowok ? 4 : 0);
            if (edge)
                cp4(sb + (512 + t) * 4, rr + ce, rowok ? sz_e : 0);
        };

        #pragma unroll
        for (int j = 0; j < DEPTH; ++j) {
            issue_row(j);
            asm volatile("cp.async.commit_group;");
        }

        float4 hw[4];                          // rolling h-filtered rows
        float* op = outp + (size_t)y0 * W_OUT + x0;

        #pragma unroll 4
        for (int r = 0; r < ROWS + 3; ++r) {
            if (r + DEPTH < ROWS + 3) issue_row(r + DEPTH);
            asm volatile("cp.async.commit_group;");       // empty group on tail
            asm volatile("cp.async.wait_group %0;" :: "n"(DEPTH - 1));
            __syncthreads();                              // row r visible

            const float* sm = ring[r & (SLOTS - 1)];
            const float4 A = *(const float4*)(sm + x0);       // x0-1 .. x0+2
            const float4 B = *(const float4*)(sm + x0 + 4);   // x0+3 .. x0+6
            float4 hc;
            hc.x = 0.25f * (A.x + A.w) + 0.75f * (A.y + A.z);
            hc.y = 0.25f * (A.y + B.x) + 0.75f * (A.z + A.w);
            hc.z = 0.25f * (A.z + B.y) + 0.75f * (A.w + B.x);
            hc.w = 0.25f * (A.w + B.z) + 0.75f * (B.x + B.y);
            hw[r & 3] = hc;

            if (r >= 3) {
                const float4 a = hw[(r - 3) & 3];
                const float4 b = hw[(r - 2) & 3];
                const float4 c = hw[(r - 1) & 3];
                float4 o;
                o.x = 0.25f * (a.x + hc.x) + 0.75f * (b.x + c.x);
                o.y = 0.25f * (a.y + hc.y) + 0.75f * (b.y + c.y);
                o.z = 0.25f * (a.z + hc.z) + 0.75f * (b.z + c.z);
                o.w = 0.25f * (a.w + hc.w) + 0.75f * (b.w + c.w);
                *(float4*)(op + (size_t)(r - 3) * W_OUT) = o;
            }
        }
    }
}

extern "C" void kernel_launch(void* const* d_in, const int* in_sizes, int n_in,
                              void* d_out, int out_size) {
    const float* in = (const float*)d_in[0];   // (4,128,513,513) f32
    float* out = (float*)d_out;                // (4,128,512,512) f32
    blur_kernel<<<GRID, NT>>>(in, out);
}

// round 7
// speedup vs baseline: 1.1962x; 1.1962x over previous
#include <cuda_runtime.h>
#include <cuda_bf16.h>
#include <cstdint>

// Blur_82471962018173: depthwise separable 4x4 FIR ([1,3,3,1]/4 per axis),
// input (4,128,513,513) f32, pad=1 both sides, output (4,128,512,512) f32.
//
// R7: 16-byte cp.async. Rows are only 4B-aligned (stride 513), so each ring
// slot holds a FLAT 16B-aligned copy of the row's stream; the per-row phase
// d = flat_start & 3 is absorbed on the compute side via 3x LDS.128 + a
// warp-uniform 4-way select. LSU warp-ops per row drop 4x vs 4B copies.

#define W_IN    513
#define W_OUT   512
#define ROWS    64
#define NT      128
#define DEPTH   6
#define SLOTS   8
#define SSTR    520                 // floats per slot (multiple of 4)
#define PLANE   (W_IN * W_IN)       // 263169
#define TOTALF  (512 * PLANE)       // total input floats (fits in int32)

__device__ __forceinline__ void cp16(uint32_t dst, const float* src, int sz) {
    asm volatile("cp.async.cg.shared.global [%0], [%1], 16, %2;"
                 :: "r"(dst), "l"(src), "r"(sz));
}

__global__ __launch_bounds__(NT, 10)
void blur_kernel(const float* __restrict__ in, float* __restrict__ out) {
    __shared__ __align__(16) float ring[SLOTS][SSTR];

    const int nc = blockIdx.z;
    const int y0 = blockIdx.y * ROWS;
    const int t  = threadIdx.x;
    const int x4 = t << 2;                       // output cols x4..x4+3

    const int pbase = nc * PLANE;                // plane flat base (int ok)
    float* __restrict__ outp = out + (size_t)nc * (W_OUT * W_OUT);

    const uint32_t sring = (uint32_t)__cvta_generic_to_shared(&ring[0][0]);

    // issue one row's flat aligned copy into its ring slot
    auto issue_row = [&](int r) {
        const int yy = y0 - 1 + r;
        const bool rowok = ((unsigned)yy < (unsigned)W_IN);
        const int a  = pbase + yy * W_IN - 1;    // flat idx of x=-1
        const int gs = a & ~3;                   // aligned copy start
        const uint32_t sb = sring + (uint32_t)(r & (SLOTS - 1)) * (SSTR * 4);

        const int gk = gs + (t << 2);
        const bool ok = rowok && (gk >= 0) && (gk + 4 <= TOTALF);
        cp16(sb + (t << 4), in + gk, ok ? 16 : 0);
        if (t < 2) {                             // chunks 128,129 -> j 512..519
            const int gk2 = gs + ((128 + t) << 2);
            const bool ok2 = rowok && (gk2 >= 0) && (gk2 + 4 <= TOTALF);
            cp16(sb + ((128 + t) << 4), in + gk2, ok2 ? 16 : 0);
        }
    };

    #pragma unroll
    for (int j = 0; j < DEPTH; ++j) {
        issue_row(j);
        asm volatile("cp.async.commit_group;");
    }

    float4 hw[4];                                // rolling h-filtered rows
    float* op = outp + (size_t)y0 * W_OUT + x4;

    #pragma unroll 4
    for (int r = 0; r < ROWS + 3; ++r) {
        if (r + DEPTH < ROWS + 3) issue_row(r + DEPTH);
        asm volatile("cp.async.commit_group;");          // empty on tail
        asm volatile("cp.async.wait_group %0;" :: "n"(DEPTH - 1));
        __syncthreads();

        const int yy = y0 - 1 + r;
        const int d  = (pbase + yy * W_IN - 1) & 3;      // block-uniform phase

        const float* sm = ring[r & (SLOTS - 1)];
        const float4 A = *(const float4*)(sm + x4);
        const float4 B = *(const float4*)(sm + x4 + 4);
        const float4 C = *(const float4*)(sm + x4 + 8);

        // window v0..v6 = in[x4-1 .. x4+5]  (smem j = x + 1 + d)
        float v0, v1, v2, v3, v4, v5, v6;
        switch (d) {
        case 0:  v0=A.x; v1=A.y; v2=A.z; v3=A.w; v4=B.x; v5=B.y; v6=B.z; break;
        case 1:  v0=A.y; v1=A.z; v2=A.w; v3=B.x; v4=B.y; v5=B.z; v6=B.w; break;
        case 2:  v0=A.z; v1=A.w; v2=B.x; v3=B.y; v4=B.z; v5=B.w; v6=C.x; break;
        default: v0=A.w; v1=B.x; v2=B.y; v3=B.z; v4=B.w; v5=C.x; v6=C.y; break;
        }
        if (t == 0)      v0 = 0.f;   // x=-1 horizontal pad
        if (t == NT - 1) v6 = 0.f;   // x=513 horizontal pad

        float4 hc;
        hc.x = 0.25f * (v0 + v3) + 0.75f * (v1 + v2);
        hc.y = 0.25f * (v1 + v4) + 0.75f * (v2 + v3);
        hc.z = 0.25f * (v2 + v5) + 0.75f * (v3 + v4);
        hc.w = 0.25f * (v3 + v6) + 0.75f * (v4 + v5);
        hw[r & 3] = hc;

        if (r >= 3) {
            const float4 a = hw[(r - 3) & 3];
            const float4 b = hw[(r - 2) & 3];
            const float4 c = hw[(r - 1) & 3];
            float4 o;
            o.x = 0.25f * (a.x + hc.x) + 0.75f * (b.x + c.x);
            o.y = 0.25f * (a.y + hc.y) + 0.75f * (b.y + c.y);
            o.z = 0.25f * (a.z + hc.z) + 0.75f * (b.z + c.z);
            o.w = 0.25f * (a.w + hc.w) + 0.75f * (b.w + c.w);
            *(float4*)(op + (size_t)(r - 3) * W_OUT) = o;
        }
    }
}

extern "C" void kernel_launch(void* const* d_in, const int* in_sizes, int n_in,
                              void* d_out, int out_size) {
    const float* in = (const float*)d_in[0];   // (4,128,513,513) f32
    float* out = (float*)d_out;                // (4,128,512,512) f32
    dim3 grid(1, W_OUT / ROWS, 4 * 128);       // 8 row-strips x 512 planes
    blur_kernel<<<grid, NT>>>(in, out);
}